// round 1
// baseline (speedup 1.0000x reference)
#include <cuda_runtime.h>
#include <cuda_bf16.h>
#include <math.h>

// Problem dims (fixed by dataset)
#define BB   4
#define LL   512
#define EE   256
#define KH   8
#define DL   6
#define KNN  4
#define GG   32000
#define LMM  64
#define BL   (BB*LL)          // 2048
#define KE   (KH*EE)          // 2048

// ---------------- static scratch (no runtime allocation allowed) -----------
__device__ float g_z   [BL*EE];
__device__ float g_xsa [BL*EE];
__device__ float g_xsad[BL*EE];
__device__ float g_tmp [BL*EE];
__device__ float g_xid [BL*EE];
__device__ float g_q   [BL*KE];            // 16 MB   [B, L*K, E]
__device__ float g_h   [BB*LL*KH*LL];      // 32 MB   [B, L*K, L]
__device__ float g_y   [BL*KE];            // 16 MB
__device__ float g_yd  [BL*KE];            // 16 MB
__device__ float g_lptok[BB*LMM*EE];
__device__ float g_xx1 [BB*LMM*KNN*EE];    // [B, 256, E]
__device__ float g_t   [BB*LMM*KNN*LL];    // [B, 256, L]
__device__ float g_xx2 [BB*LMM*KNN*EE];
__device__ float g_v   [BB*LMM*KNN*EE];
__device__ float g_logits[(long)BB*LMM*KNN*GG]; // 131 MB [1024, 32000]
__device__ float g_lse [BB*LMM*KNN];

// ---------------- block reductions (256 threads) ---------------------------
__device__ __forceinline__ float blkSum256(float v) {
    __shared__ float sh[8];
    int lane = threadIdx.x & 31, w = threadIdx.x >> 5;
    #pragma unroll
    for (int o = 16; o; o >>= 1) v += __shfl_xor_sync(0xffffffffu, v, o);
    __syncthreads();
    if (lane == 0) sh[w] = v;
    __syncthreads();
    float r = sh[0];
    #pragma unroll
    for (int i = 1; i < 8; i++) r += sh[i];
    return r;
}
__device__ __forceinline__ float blkMax256(float v) {
    __shared__ float sh[8];
    int lane = threadIdx.x & 31, w = threadIdx.x >> 5;
    #pragma unroll
    for (int o = 16; o; o >>= 1) v = fmaxf(v, __shfl_xor_sync(0xffffffffu, v, o));
    __syncthreads();
    if (lane == 0) sh[w] = v;
    __syncthreads();
    float r = sh[0];
    #pragma unroll
    for (int i = 1; i < 8; i++) r = fmaxf(r, sh[i]);
    return r;
}

// ---------------- generic tiled GEMM ---------------------------------------
// C[M,N] (+)= relu?( alpha * A(roll)[M,K] * B(^T)[K,N] + bias[n] )
// flags: bit0 = transB (B stored [N,K]), bit1 = relu, bit2 = accumulate
#define FL_TRANS 1
#define FL_RELU  2
#define FL_ACC   4

__global__ __launch_bounds__(256) void gemm_k(
    const float* __restrict__ A, const float* __restrict__ Bm,
    const float* __restrict__ bias, float* __restrict__ C,
    int M, int N, int Kd, long sA, long sB, long sC,
    int rollL, int rollOff, float alpha, int flags)
{
    A  += (long)blockIdx.z * sA;
    Bm += (long)blockIdx.z * sB;
    C  += (long)blockIdx.z * sC;
    const bool transB = flags & FL_TRANS;
    const bool doRelu = flags & FL_RELU;
    const bool accum  = flags & FL_ACC;

    __shared__ float As[32][64];   // As[k][m]
    __shared__ float Bs[32][64];   // Bs[k][n]

    int tid = threadIdx.x;
    int tx = tid & 15, ty = tid >> 4;
    int m0 = blockIdx.y * 64, n0 = blockIdx.x * 64;

    float acc[4][4] = {};

    // A loader: row = tid>>2 (0..63), k offset = (tid&3)*8
    int arow = tid >> 2;
    int ak0  = (tid & 3) * 8;
    int gm = m0 + arow;
    if (rollL) {
        int g = gm / rollL, l = gm - g * rollL;
        l += rollOff; if (l >= rollL) l -= rollL;
        gm = g * rollL + l;
    }
    const float* Aptr = A + (long)gm * Kd + ak0;

    for (int k0 = 0; k0 < Kd; k0 += 32) {
        #pragma unroll
        for (int i = 0; i < 8; i += 4) {
            float4 v = *(const float4*)(Aptr + k0 + i);
            As[ak0+i+0][arow] = v.x; As[ak0+i+1][arow] = v.y;
            As[ak0+i+2][arow] = v.z; As[ak0+i+3][arow] = v.w;
        }
        if (transB) {
            int brow = tid >> 2, bk0 = (tid & 3) * 8;
            const float* Bp = Bm + (long)(n0 + brow) * Kd + k0 + bk0;
            #pragma unroll
            for (int i = 0; i < 8; i += 4) {
                float4 v = *(const float4*)(Bp + i);
                Bs[bk0+i+0][brow] = v.x; Bs[bk0+i+1][brow] = v.y;
                Bs[bk0+i+2][brow] = v.z; Bs[bk0+i+3][brow] = v.w;
            }
        } else {
            int bk = tid >> 3, bn0 = (tid & 7) * 8;
            const float* Bp = Bm + (long)(k0 + bk) * N + n0 + bn0;
            #pragma unroll
            for (int i = 0; i < 8; i += 4) {
                float4 v = *(const float4*)(Bp + i);
                *(float4*)&Bs[bk][bn0 + i] = v;
            }
        }
        __syncthreads();
        #pragma unroll
        for (int k = 0; k < 32; k++) {
            float a[4], b[4];
            *(float4*)a = *(const float4*)&As[k][ty * 4];
            *(float4*)b = *(const float4*)&Bs[k][tx * 4];
            #pragma unroll
            for (int i = 0; i < 4; i++)
                #pragma unroll
                for (int j = 0; j < 4; j++)
                    acc[i][j] += a[i] * b[j];
        }
        __syncthreads();
    }

    #pragma unroll
    for (int i = 0; i < 4; i++) {
        int m = m0 + ty * 4 + i;
        #pragma unroll
        for (int j = 0; j < 4; j++) {
            int n = n0 + tx * 4 + j;
            float v = alpha * acc[i][j];
            if (bias) v += bias[n];
            if (doRelu) v = fmaxf(v, 0.f);
            long idx = (long)m * N + n;
            if (accum) C[idx] += v; else C[idx] = v;
        }
    }
}

// ---------------- elementwise / reduction kernels --------------------------
__global__ void embed_norm_k(const int* __restrict__ masked,
                             const float* __restrict__ embed,
                             float* __restrict__ z, float* __restrict__ xsa)
{
    long row = blockIdx.x; int t = threadIdx.x;
    float v = embed[(long)masked[row] * EE + t];
    float mean = blkSum256(v) * (1.f / EE);
    float d = v - mean;
    float var = fmaxf(blkSum256(d * d) * (1.f / (EE - 1)), 0.f);
    float o = v / (1.f + sqrtf(var));
    z[row * EE + t] = o;
    xsa[row * EE + t] = o;
}

__global__ void softmax512_k(float* __restrict__ h) {
    long row = blockIdx.x;
    float* p = h + row * 512;
    int t = threadIdx.x;
    float a = p[t], b = p[t + 256];
    float m = blkMax256(fmaxf(a, b));
    float ea = expf(a - m), eb = expf(b - m);
    float s = blkSum256(ea + eb);
    float inv = 1.f / s;
    p[t] = ea * inv; p[t + 256] = eb * inv;
}

__global__ void update_k(const float* __restrict__ xsad,
                         const float* __restrict__ xid,
                         float* __restrict__ xsa)
{
    long row = blockIdx.x; int t = threadIdx.x;
    long i = row * EE + t;
    float s = xsad[i] + xid[i];
    float mean = blkSum256(s) * (1.f / EE);
    float d = s - mean;
    float var = fmaxf(blkSum256(d * d) * (1.f / (EE - 1)), 0.f);
    float a = s / (1.f + sqrtf(var));
    float x = xsa[i] + 0.05f * a;
    float mean2 = blkSum256(x) * (1.f / EE);
    float d2 = x - mean2;
    float var2 = fmaxf(blkSum256(d2 * d2) * (1.f / (EE - 1)), 0.f);
    xsa[i] = x / (1.f + sqrtf(var2));
}

__global__ void gather_lptok_k(const float* __restrict__ xsa,
                               const int* __restrict__ mask,
                               float* __restrict__ lptok)
{
    int r = blockIdx.x;              // 0..B*LM-1
    int b = r / LMM, lm = r % LMM;
    int pos = mask[b * LMM + lm];
    int t = threadIdx.x;
    lptok[(long)r * EE + t] = xsa[((long)b * LL + pos) * EE + t];
}

__global__ void lse_k(const float* __restrict__ logits, float* __restrict__ lse) {
    long row = blockIdx.x;
    const float* p = logits + row * GG;
    int t = threadIdx.x;
    float m = -1e30f;
    for (int i = t; i < GG; i += 256) m = fmaxf(m, p[i]);
    m = blkMax256(m);
    float s = 0.f;
    for (int i = t; i < GG; i += 256) s += expf(p[i] - m);
    s = blkSum256(s);
    if (!t) lse[row] = m + logf(s);
}

__global__ void final_k(const float* __restrict__ logits,
                        const float* __restrict__ lse,
                        const int* __restrict__ unmasked,
                        const int* __restrict__ mask,
                        float* __restrict__ out)
{
    int b = blockIdx.x, lm = threadIdx.x;   // 64 threads
    int pos = mask[b * LMM + lm];
    int tgt = unmasked[b * LL + pos];
    float v[KNN]; float m = -1e30f;
    #pragma unroll
    for (int kn = 0; kn < KNN; kn++) {
        int n = b * (LMM * KNN) + lm * KNN + kn;
        v[kn] = logits[(long)n * GG + tgt] - lse[n];
        m = fmaxf(m, v[kn]);
    }
    float s = 0.f;
    #pragma unroll
    for (int kn = 0; kn < KNN; kn++) s += expf(v[kn] - m);
    float cent = m + logf(s) - logf((float)KNN);
    __shared__ float sh[LMM];
    sh[lm] = cent; __syncthreads();
    for (int o = 32; o; o >>= 1) { if (lm < o) sh[lm] += sh[lm + o]; __syncthreads(); }
    if (!lm) out[b] = -sh[0] / (float)LMM;
}

// ---------------- host orchestration ---------------------------------------
static inline void gemm(const float* A, const float* B, const float* bias, float* C,
                        int M, int N, int K, long sA, long sB, long sC, int batch,
                        int rollL, int rollOff, float alpha, int flags)
{
    dim3 g(N / 64, M / 64, batch);
    gemm_k<<<g, 256>>>(A, B, bias, C, M, N, K, sA, sB, sC, rollL, rollOff, alpha, flags);
}

template <typename T>
static inline T* sym(const void* s) {
    void* p = nullptr;
    cudaGetSymbolAddress(&p, s);
    return (T*)p;
}

extern "C" void kernel_launch(void* const* d_in, const int* in_sizes, int n_in,
                              void* d_out, int out_size)
{
    const int*   masked   = (const int*)  d_in[0];
    const int*   unmasked = (const int*)  d_in[1];
    const int*   mask     = (const int*)  d_in[2];
    const float* embed    = (const float*)d_in[3];
    const float* Wt       = (const float*)d_in[4];
    const float* bt       = (const float*)d_in[5];
    const float* Wtc      = (const float*)d_in[6];
    const float* Wq       = (const float*)d_in[7];
    const float* Wd       = (const float*)d_in[8];
    const float* Wo       = (const float*)d_in[9];
    const float* Wu       = (const float*)d_in[10];
    const float* Wem      = (const float*)d_in[11];
    const float* Wkc      = (const float*)d_in[12];
    const float* bkc      = (const float*)d_in[13];
    float* out = (float*)d_out;

    float* z    = sym<float>(g_z);
    float* xsa  = sym<float>(g_xsa);
    float* xsad = sym<float>(g_xsad);
    float* tmp  = sym<float>(g_tmp);
    float* xid  = sym<float>(g_xid);
    float* q    = sym<float>(g_q);
    float* h    = sym<float>(g_h);
    float* y    = sym<float>(g_y);
    float* yd   = sym<float>(g_yd);
    float* lptok= sym<float>(g_lptok);
    float* xx1  = sym<float>(g_xx1);
    float* tbuf = sym<float>(g_t);
    float* xx2  = sym<float>(g_xx2);
    float* v    = sym<float>(g_v);
    float* logits = sym<float>(g_logits);
    float* lse  = sym<float>(g_lse);

    // input image: z = norm(embed[masked]); xsa = z
    embed_norm_k<<<BL, 256>>>(masked, embed, z, xsa);

    const float inv_sqrt_e = 1.f / 16.f;   // 1/sqrt(256)

    for (int d = 0; d < DL; d++) {
        const float* wt  = Wt  + (long)d * EE * EE;
        const float* btd = bt  + (long)d * EE;
        const float* wtc = Wtc + (long)d * EE * EE;
        const float* wq  = Wq  + (long)d * KE * EE;
        const float* wd  = Wd  + (long)d * KE * KE;
        const float* wo  = Wo  + (long)d * KE * EE;
        const float* wu  = Wu  + (long)d * EE * EE;

        // xsad = relu(roll(xsa,+1) @ wt) @ wtc
        gemm(xsa, wt,  nullptr, tmp,  BL, EE, EE, 0,0,0, 1, LL, LL-1, 1.f, FL_RELU);
        gemm(tmp, wtc, nullptr, xsad, BL, EE, EE, 0,0,0, 1, 0, 0,    1.f, 0);
        // xsad += relu(roll(xsa,-1) @ wtc.T) @ wt.T
        gemm(xsa, wtc, nullptr, tmp,  BL, EE, EE, 0,0,0, 1, LL, 1,   1.f, FL_TRANS | FL_RELU);
        gemm(tmp, wt,  nullptr, xsad, BL, EE, EE, 0,0,0, 1, 0, 0,    1.f, FL_TRANS | FL_ACC);
        // xsad += z @ wu.T + bt
        gemm(z,   wu,  btd,     xsad, BL, EE, EE, 0,0,0, 1, 0, 0,    1.f, FL_TRANS | FL_ACC);
        // q = xsa @ wq.T          -> [B, L*K, E] contiguous
        gemm(xsa, wq,  nullptr, q,    BL, KE, EE, 0,0,0, 1, 0, 0,    1.f, FL_TRANS);
        // h[b] = (1/sqrt(E)) * Q[b] @ xsa[b]^T : [L*K, L]
        gemm(q, xsa, nullptr, h, LL*KH, LL, EE,
             (long)LL*KE, (long)LL*EE, (long)LL*KH*LL, BB, 0, 0, inv_sqrt_e, FL_TRANS);
        softmax512_k<<<BB * LL * KH, 256>>>(h);
        // y[b] = P[b] @ xsa[b] : [L*K, E] == [B, L, K*E]
        gemm(h, xsa, nullptr, y, LL*KH, EE, LL,
             (long)LL*KH*LL, (long)LL*EE, (long)LL*KH*EE, BB, 0, 0, 1.f, 0);
        // yd = relu(y @ wd.T); xid = yd @ wo
        gemm(y,  wd, nullptr, yd,  BL, KE, KE, 0,0,0, 1, 0, 0, 1.f, FL_TRANS | FL_RELU);
        gemm(yd, wo, nullptr, xid, BL, EE, KE, 0,0,0, 1, 0, 0, 1.f, 0);
        // xsa = norm(xsa + 0.05*norm(xsad + xid))
        update_k<<<BL, 256>>>(xsad, xid, xsa);
    }

    // ---- head ----
    gather_lptok_k<<<BB * LMM, 256>>>(xsa, mask, lptok);
    // xx1 = lptok @ Wkc.T + bkc  -> [B, LM*KN, E] contiguous
    gemm(lptok, Wkc, bkc, xx1, BB*LMM, KNN*EE, EE, 0,0,0, 1, 0, 0, 1.f, FL_TRANS);
    // t[b] = xx1[b] @ xsa[b]^T : [256, L]
    gemm(xx1, xsa, nullptr, tbuf, LMM*KNN, LL, EE,
         (long)LMM*KNN*EE, (long)LL*EE, (long)LMM*KNN*LL, BB, 0, 0, 1.f, FL_TRANS);
    // xx2[b] = t[b] @ xsa[b] : [256, E]
    gemm(tbuf, xsa, nullptr, xx2, LMM*KNN, EE, LL,
         (long)LMM*KNN*LL, (long)LL*EE, (long)LMM*KNN*EE, BB, 0, 0, 1.f, 0);
    // v = xx2 @ Wem  (flatten batch: [1024, E])
    gemm(xx2, Wem, nullptr, v, BB*LMM*KNN, EE, EE, 0,0,0, 1, 0, 0, 1.f, 0);
    // logits = v @ embed.T : [1024, 32000]
    gemm(v, embed, nullptr, logits, BB*LMM*KNN, GG, EE, 0,0,0, 1, 0, 0, 1.f, FL_TRANS);
    // per-row logsumexp over G
    lse_k<<<BB * LMM * KNN, 256>>>(logits, lse);
    // final cross-entropy -> out[B]
    final_k<<<BB, LMM>>>(logits, lse, unmasked, mask, out);
}

// round 2
// speedup vs baseline: 1.1625x; 1.1625x over previous
#include <cuda_runtime.h>
#include <cuda_bf16.h>
#include <math.h>

// Problem dims (fixed by dataset)
#define BB   4
#define LL   512
#define EE   256
#define KH   8
#define DL   6
#define KNN  4
#define GG   32000
#define LMM  64
#define BL   (BB*LL)          // 2048
#define KE   (KH*EE)          // 2048

// ---------------- static scratch (no runtime allocation allowed) -----------
__device__ float g_z   [BL*EE];
__device__ float g_xsa [BL*EE];
__device__ float g_xsad[BL*EE];
__device__ float g_tmp [BL*EE];
__device__ float g_xid [BL*EE];
__device__ float g_q   [BL*KE];            // 16 MB   [B, L*K, E]
__device__ float g_h   [BB*LL*KH*LL];      // 32 MB   [B, L*K, L]
__device__ float g_y   [BL*KE];            // 16 MB
__device__ float g_yd  [BL*KE];            // 16 MB
__device__ float g_lptok[BB*LMM*EE];
__device__ float g_xx1 [BB*LMM*KNN*EE];    // [B, 256, E]
__device__ float g_t   [BB*LMM*KNN*LL];    // [B, 256, L]
__device__ float g_xx2 [BB*LMM*KNN*EE];
__device__ float g_v   [BB*LMM*KNN*EE];
__device__ float g_logits[(long)BB*LMM*KNN*GG]; // 131 MB [1024, 32000]
__device__ float g_lse [BB*LMM*KNN];

// flags
#define FL_TRANS 1
#define FL_RELU  2
#define FL_ACC   4
#define FL_ATOM  8

// ---------------- block reductions (256 threads) ---------------------------
__device__ __forceinline__ float blkSum256(float v) {
    __shared__ float sh[8];
    int lane = threadIdx.x & 31, w = threadIdx.x >> 5;
    #pragma unroll
    for (int o = 16; o; o >>= 1) v += __shfl_xor_sync(0xffffffffu, v, o);
    __syncthreads();
    if (lane == 0) sh[w] = v;
    __syncthreads();
    float r = sh[0];
    #pragma unroll
    for (int i = 1; i < 8; i++) r += sh[i];
    return r;
}
__device__ __forceinline__ float blkMax256(float v) {
    __shared__ float sh[8];
    int lane = threadIdx.x & 31, w = threadIdx.x >> 5;
    #pragma unroll
    for (int o = 16; o; o >>= 1) v = fmaxf(v, __shfl_xor_sync(0xffffffffu, v, o));
    __syncthreads();
    if (lane == 0) sh[w] = v;
    __syncthreads();
    float r = sh[0];
    #pragma unroll
    for (int i = 1; i < 8; i++) r = fmaxf(r, sh[i]);
    return r;
}

__device__ __forceinline__ int roll_row(int gm, int rollL, int rollOff) {
    if (!rollL) return gm;
    int g = gm / rollL, l = gm - g * rollL;
    l += rollOff; if (l >= rollL) l -= rollL;
    return g * rollL + l;
}

// ---------------- 64x64 tiled GEMM (small grids / split-K) -----------------
// C[M,N] (+)= relu?( alpha * A(roll)[M,K] * B(^T)[K,N] + bias[n] )
__global__ __launch_bounds__(256) void gemm_k(
    const float* __restrict__ A, const float* __restrict__ Bm,
    const float* __restrict__ bias, float* __restrict__ C,
    int M, int N, int Kd, long sA, long sB, long sC,
    int rollL, int rollOff, float alpha, int flags, int splitK, int Kc)
{
    int bz = blockIdx.z;
    int batch = bz, kb = 0, ke = Kd;
    if (splitK > 1) {
        batch = bz / splitK;
        int c = bz % splitK;
        kb = c * Kc; ke = min(Kd, kb + Kc);
    }
    A  += (long)batch * sA;
    Bm += (long)batch * sB;
    C  += (long)batch * sC;
    const bool transB = flags & FL_TRANS;
    const bool doRelu = flags & FL_RELU;
    const bool accum  = flags & FL_ACC;
    const bool atom   = flags & FL_ATOM;

    __shared__ float As[32][64];   // As[k][m]
    __shared__ float Bs[32][64];   // Bs[k][n]

    int tid = threadIdx.x;
    int tx = tid & 15, ty = tid >> 4;
    int m0 = blockIdx.y * 64, n0 = blockIdx.x * 64;

    float acc[4][4] = {};

    int arow = tid >> 2;
    int ak0  = (tid & 3) * 8;
    int gm = roll_row(m0 + arow, rollL, rollOff);
    const float* Aptr = A + (long)gm * Kd + ak0;

    for (int k0 = kb; k0 < ke; k0 += 32) {
        #pragma unroll
        for (int i = 0; i < 8; i += 4) {
            float4 v = *(const float4*)(Aptr + k0 + i);
            As[ak0+i+0][arow] = v.x; As[ak0+i+1][arow] = v.y;
            As[ak0+i+2][arow] = v.z; As[ak0+i+3][arow] = v.w;
        }
        if (transB) {
            int brow = tid >> 2, bk0 = (tid & 3) * 8;
            const float* Bp = Bm + (long)(n0 + brow) * Kd + k0 + bk0;
            #pragma unroll
            for (int i = 0; i < 8; i += 4) {
                float4 v = *(const float4*)(Bp + i);
                Bs[bk0+i+0][brow] = v.x; Bs[bk0+i+1][brow] = v.y;
                Bs[bk0+i+2][brow] = v.z; Bs[bk0+i+3][brow] = v.w;
            }
        } else {
            int bk = tid >> 3, bn0 = (tid & 7) * 8;
            const float* Bp = Bm + (long)(k0 + bk) * N + n0 + bn0;
            #pragma unroll
            for (int i = 0; i < 8; i += 4) {
                float4 v = *(const float4*)(Bp + i);
                *(float4*)&Bs[bk][bn0 + i] = v;
            }
        }
        __syncthreads();
        #pragma unroll
        for (int k = 0; k < 32; k++) {
            float a[4], b[4];
            *(float4*)a = *(const float4*)&As[k][ty * 4];
            *(float4*)b = *(const float4*)&Bs[k][tx * 4];
            #pragma unroll
            for (int i = 0; i < 4; i++)
                #pragma unroll
                for (int j = 0; j < 4; j++)
                    acc[i][j] += a[i] * b[j];
        }
        __syncthreads();
    }

    #pragma unroll
    for (int i = 0; i < 4; i++) {
        int m = m0 + ty * 4 + i;
        #pragma unroll
        for (int j = 0; j < 4; j++) {
            int n = n0 + tx * 4 + j;
            float v = alpha * acc[i][j];
            if (bias) v += bias[n];
            if (doRelu) v = fmaxf(v, 0.f);
            long idx = (long)m * N + n;
            if (atom) atomicAdd(&C[idx], v);
            else if (accum) C[idx] += v;
            else C[idx] = v;
        }
    }
}

// ---------------- 128x128x16 double-buffered GEMM --------------------------
__global__ __launch_bounds__(256) void gemm128_k(
    const float* __restrict__ A, const float* __restrict__ Bm,
    const float* __restrict__ bias, float* __restrict__ C,
    int M, int N, int Kd, long sA, long sB, long sC,
    int rollL, int rollOff, float alpha, int flags)
{
    A  += (long)blockIdx.z * sA;
    Bm += (long)blockIdx.z * sB;
    C  += (long)blockIdx.z * sC;
    const bool transB = flags & FL_TRANS;
    const bool doRelu = flags & FL_RELU;
    const bool accum  = flags & FL_ACC;

    __shared__ float As[2][16][128];
    __shared__ float Bs[2][16][128];

    int tid = threadIdx.x;
    int tx = tid & 15, ty = tid >> 4;
    int m0 = blockIdx.y * 128, n0 = blockIdx.x * 128;

    // A loader: rows ar, ar+64 ; k quad ak..ak+3
    int ar = tid >> 2;
    int ak = (tid & 3) * 4;
    int gm1 = roll_row(m0 + ar,      rollL, rollOff);
    int gm2 = roll_row(m0 + ar + 64, rollL, rollOff);
    const float* Ap1 = A + (long)gm1 * Kd + ak;
    const float* Ap2 = A + (long)gm2 * Kd + ak;

    // B loader
    const float *Bp1 = nullptr, *Bp2 = nullptr;
    int bn = 0, bk = 0, br = 0;
    if (transB) {
        br = tid >> 2;
        Bp1 = Bm + (long)(n0 + br)      * Kd + ak;
        Bp2 = Bm + (long)(n0 + br + 64) * Kd + ak;
    } else {
        bk = tid >> 5;           // 0..7
        bn = (tid & 31) * 4;     // 0..124
        Bp1 = Bm + (long)bk * N + n0 + bn;
        Bp2 = Bm + (long)(bk + 8) * N + n0 + bn;
    }

    float acc[8][8] = {};
    float4 ra1, ra2, rb1, rb2;

    // prologue: load tile 0
    ra1 = *(const float4*)(Ap1);
    ra2 = *(const float4*)(Ap2);
    if (transB) { rb1 = *(const float4*)(Bp1); rb2 = *(const float4*)(Bp2); }
    else        { rb1 = *(const float4*)(Bp1); rb2 = *(const float4*)(Bp2); }
    {
        As[0][ak+0][ar] = ra1.x; As[0][ak+1][ar] = ra1.y; As[0][ak+2][ar] = ra1.z; As[0][ak+3][ar] = ra1.w;
        As[0][ak+0][ar+64] = ra2.x; As[0][ak+1][ar+64] = ra2.y; As[0][ak+2][ar+64] = ra2.z; As[0][ak+3][ar+64] = ra2.w;
        if (transB) {
            Bs[0][ak+0][br] = rb1.x; Bs[0][ak+1][br] = rb1.y; Bs[0][ak+2][br] = rb1.z; Bs[0][ak+3][br] = rb1.w;
            Bs[0][ak+0][br+64] = rb2.x; Bs[0][ak+1][br+64] = rb2.y; Bs[0][ak+2][br+64] = rb2.z; Bs[0][ak+3][br+64] = rb2.w;
        } else {
            *(float4*)&Bs[0][bk][bn] = rb1;
            *(float4*)&Bs[0][bk+8][bn] = rb2;
        }
    }
    __syncthreads();

    const int nT = Kd >> 4;
    int buf = 0;
    for (int t = 0; t < nT; t++) {
        if (t + 1 < nT) {
            int k0 = (t + 1) << 4;
            ra1 = *(const float4*)(Ap1 + k0);
            ra2 = *(const float4*)(Ap2 + k0);
            if (transB) {
                rb1 = *(const float4*)(Bp1 + k0);
                rb2 = *(const float4*)(Bp2 + k0);
            } else {
                rb1 = *(const float4*)(Bp1 + (long)k0 * N);
                rb2 = *(const float4*)(Bp2 + (long)k0 * N);
            }
        }
        #pragma unroll
        for (int k = 0; k < 16; k++) {
            float a[8], b[8];
            *(float4*)(a)     = *(const float4*)&As[buf][k][ty * 8];
            *(float4*)(a + 4) = *(const float4*)&As[buf][k][ty * 8 + 4];
            *(float4*)(b)     = *(const float4*)&Bs[buf][k][tx * 8];
            *(float4*)(b + 4) = *(const float4*)&Bs[buf][k][tx * 8 + 4];
            #pragma unroll
            for (int i = 0; i < 8; i++)
                #pragma unroll
                for (int j = 0; j < 8; j++)
                    acc[i][j] += a[i] * b[j];
        }
        if (t + 1 < nT) {
            int nb = buf ^ 1;
            As[nb][ak+0][ar] = ra1.x; As[nb][ak+1][ar] = ra1.y; As[nb][ak+2][ar] = ra1.z; As[nb][ak+3][ar] = ra1.w;
            As[nb][ak+0][ar+64] = ra2.x; As[nb][ak+1][ar+64] = ra2.y; As[nb][ak+2][ar+64] = ra2.z; As[nb][ak+3][ar+64] = ra2.w;
            if (transB) {
                Bs[nb][ak+0][br] = rb1.x; Bs[nb][ak+1][br] = rb1.y; Bs[nb][ak+2][br] = rb1.z; Bs[nb][ak+3][br] = rb1.w;
                Bs[nb][ak+0][br+64] = rb2.x; Bs[nb][ak+1][br+64] = rb2.y; Bs[nb][ak+2][br+64] = rb2.z; Bs[nb][ak+3][br+64] = rb2.w;
            } else {
                *(float4*)&Bs[nb][bk][bn] = rb1;
                *(float4*)&Bs[nb][bk+8][bn] = rb2;
            }
            __syncthreads();
            buf = nb;
        }
    }

    #pragma unroll
    for (int i = 0; i < 8; i++) {
        int m = m0 + ty * 8 + i;
        float* Crow = C + (long)m * N + n0 + tx * 8;
        if (accum) {
            #pragma unroll
            for (int j = 0; j < 8; j++) {
                float v = alpha * acc[i][j];
                if (bias) v += bias[n0 + tx * 8 + j];
                if (doRelu) v = fmaxf(v, 0.f);
                Crow[j] += v;
            }
        } else {
            float4 o0, o1;
            float tmpv[8];
            #pragma unroll
            for (int j = 0; j < 8; j++) {
                float v = alpha * acc[i][j];
                if (bias) v += bias[n0 + tx * 8 + j];
                if (doRelu) v = fmaxf(v, 0.f);
                tmpv[j] = v;
            }
            o0 = make_float4(tmpv[0], tmpv[1], tmpv[2], tmpv[3]);
            o1 = make_float4(tmpv[4], tmpv[5], tmpv[6], tmpv[7]);
            *(float4*)(Crow)     = o0;
            *(float4*)(Crow + 4) = o1;
        }
    }
}

// ---------------- elementwise / reduction kernels --------------------------
__global__ void embed_norm_k(const int* __restrict__ masked,
                             const float* __restrict__ embed,
                             float* __restrict__ z, float* __restrict__ xsa)
{
    long row = blockIdx.x; int t = threadIdx.x;
    float v = embed[(long)masked[row] * EE + t];
    float mean = blkSum256(v) * (1.f / EE);
    float d = v - mean;
    float var = fmaxf(blkSum256(d * d) * (1.f / (EE - 1)), 0.f);
    float o = v / (1.f + sqrtf(var));
    z[row * EE + t] = o;
    xsa[row * EE + t] = o;
}

__global__ void softmax512_k(float* __restrict__ h) {
    long row = blockIdx.x;
    float* p = h + row * 512;
    int t = threadIdx.x;
    float a = p[t], b = p[t + 256];
    float m = blkMax256(fmaxf(a, b));
    float ea = expf(a - m), eb = expf(b - m);
    float s = blkSum256(ea + eb);
    float inv = 1.f / s;
    p[t] = ea * inv; p[t + 256] = eb * inv;
}

__global__ void update_k(const float* __restrict__ xsad,
                         const float* __restrict__ xid,
                         float* __restrict__ xsa)
{
    long row = blockIdx.x; int t = threadIdx.x;
    long i = row * EE + t;
    float s = xsad[i] + xid[i];
    float mean = blkSum256(s) * (1.f / EE);
    float d = s - mean;
    float var = fmaxf(blkSum256(d * d) * (1.f / (EE - 1)), 0.f);
    float a = s / (1.f + sqrtf(var));
    float x = xsa[i] + 0.05f * a;
    float mean2 = blkSum256(x) * (1.f / EE);
    float d2 = x - mean2;
    float var2 = fmaxf(blkSum256(d2 * d2) * (1.f / (EE - 1)), 0.f);
    xsa[i] = x / (1.f + sqrtf(var2));
}

__global__ void gather_lptok_k(const float* __restrict__ xsa,
                               const int* __restrict__ mask,
                               float* __restrict__ lptok)
{
    int r = blockIdx.x;
    int b = r / LMM, lm = r % LMM;
    int pos = mask[b * LMM + lm];
    int t = threadIdx.x;
    lptok[(long)r * EE + t] = xsa[((long)b * LL + pos) * EE + t];
}

__global__ void lse_k(const float* __restrict__ logits, float* __restrict__ lse) {
    long row = blockIdx.x;
    const float* p = logits + row * GG;
    int t = threadIdx.x;
    float m = -1e30f;
    for (int i = t; i < GG; i += 256) m = fmaxf(m, p[i]);
    m = blkMax256(m);
    float s = 0.f;
    for (int i = t; i < GG; i += 256) s += expf(p[i] - m);
    s = blkSum256(s);
    if (!t) lse[row] = m + logf(s);
}

__global__ void final_k(const float* __restrict__ logits,
                        const float* __restrict__ lse,
                        const int* __restrict__ unmasked,
                        const int* __restrict__ mask,
                        float* __restrict__ out)
{
    int b = blockIdx.x, lm = threadIdx.x;   // 64 threads
    int pos = mask[b * LMM + lm];
    int tgt = unmasked[b * LL + pos];
    float v[KNN]; float m = -1e30f;
    #pragma unroll
    for (int kn = 0; kn < KNN; kn++) {
        int n = b * (LMM * KNN) + lm * KNN + kn;
        v[kn] = logits[(long)n * GG + tgt] - lse[n];
        m = fmaxf(m, v[kn]);
    }
    float s = 0.f;
    #pragma unroll
    for (int kn = 0; kn < KNN; kn++) s += expf(v[kn] - m);
    float cent = m + logf(s) - logf((float)KNN);
    __shared__ float sh[LMM];
    sh[lm] = cent; __syncthreads();
    for (int o = 32; o; o >>= 1) { if (lm < o) sh[lm] += sh[lm + o]; __syncthreads(); }
    if (!lm) out[b] = -sh[0] / (float)LMM;
}

// ---------------- host orchestration ---------------------------------------
static inline void gemm(const float* A, const float* B, const float* bias, float* C,
                        int M, int N, int K, long sA, long sB, long sC, int batch,
                        int rollL, int rollOff, float alpha, int flags, int splitK = 1)
{
    long blocks128 = (M % 128 == 0 && N % 128 == 0 && K % 16 == 0)
                   ? (long)(M / 128) * (N / 128) * batch : 0;
    if (splitK == 1 && blocks128 >= 96) {
        dim3 g(N / 128, M / 128, batch);
        gemm128_k<<<g, 256>>>(A, B, bias, C, M, N, K, sA, sB, sC, rollL, rollOff, alpha, flags);
    } else {
        int Kc = K;
        if (splitK > 1) {
            Kc = (K + splitK - 1) / splitK;
            Kc = ((Kc + 31) / 32) * 32;
            flags |= FL_ATOM;
        }
        dim3 g(N / 64, M / 64, batch * splitK);
        gemm_k<<<g, 256>>>(A, B, bias, C, M, N, K, sA, sB, sC, rollL, rollOff, alpha, flags, splitK, Kc);
    }
}

template <typename T>
static inline T* sym(const void* s) {
    void* p = nullptr;
    cudaGetSymbolAddress(&p, s);
    return (T*)p;
}

extern "C" void kernel_launch(void* const* d_in, const int* in_sizes, int n_in,
                              void* d_out, int out_size)
{
    const int*   masked   = (const int*)  d_in[0];
    const int*   unmasked = (const int*)  d_in[1];
    const int*   mask     = (const int*)  d_in[2];
    const float* embed    = (const float*)d_in[3];
    const float* Wt       = (const float*)d_in[4];
    const float* bt       = (const float*)d_in[5];
    const float* Wtc      = (const float*)d_in[6];
    const float* Wq       = (const float*)d_in[7];
    const float* Wd       = (const float*)d_in[8];
    const float* Wo       = (const float*)d_in[9];
    const float* Wu       = (const float*)d_in[10];
    const float* Wem      = (const float*)d_in[11];
    const float* Wkc      = (const float*)d_in[12];
    const float* bkc      = (const float*)d_in[13];
    float* out = (float*)d_out;

    float* z    = sym<float>(g_z);
    float* xsa  = sym<float>(g_xsa);
    float* xsad = sym<float>(g_xsad);
    float* tmp  = sym<float>(g_tmp);
    float* xid  = sym<float>(g_xid);
    float* q    = sym<float>(g_q);
    float* h    = sym<float>(g_h);
    float* y    = sym<float>(g_y);
    float* yd   = sym<float>(g_yd);
    float* lptok= sym<float>(g_lptok);
    float* xx1  = sym<float>(g_xx1);
    float* tbuf = sym<float>(g_t);
    float* xx2  = sym<float>(g_xx2);
    float* v    = sym<float>(g_v);
    float* logits = sym<float>(g_logits);
    float* lse  = sym<float>(g_lse);

    embed_norm_k<<<BL, 256>>>(masked, embed, z, xsa);

    const float inv_sqrt_e = 1.f / 16.f;   // 1/sqrt(256)

    for (int d = 0; d < DL; d++) {
        const float* wt  = Wt  + (long)d * EE * EE;
        const float* btd = bt  + (long)d * EE;
        const float* wtc = Wtc + (long)d * EE * EE;
        const float* wq  = Wq  + (long)d * KE * EE;
        const float* wd  = Wd  + (long)d * KE * KE;
        const float* wo  = Wo  + (long)d * KE * EE;
        const float* wu  = Wu  + (long)d * EE * EE;

        // xsad = relu(roll(xsa,+1) @ wt) @ wtc
        gemm(xsa, wt,  nullptr, tmp,  BL, EE, EE, 0,0,0, 1, LL, LL-1, 1.f, FL_RELU);
        gemm(tmp, wtc, nullptr, xsad, BL, EE, EE, 0,0,0, 1, 0, 0,    1.f, 0);
        // xsad += relu(roll(xsa,-1) @ wtc.T) @ wt.T
        gemm(xsa, wtc, nullptr, tmp,  BL, EE, EE, 0,0,0, 1, LL, 1,   1.f, FL_TRANS | FL_RELU);
        gemm(tmp, wt,  nullptr, xsad, BL, EE, EE, 0,0,0, 1, 0, 0,    1.f, FL_TRANS | FL_ACC);
        // xsad += z @ wu.T + bt
        gemm(z,   wu,  btd,     xsad, BL, EE, EE, 0,0,0, 1, 0, 0,    1.f, FL_TRANS | FL_ACC);
        // q = xsa @ wq.T
        gemm(xsa, wq,  nullptr, q,    BL, KE, EE, 0,0,0, 1, 0, 0,    1.f, FL_TRANS);
        // h[b] = (1/sqrt(E)) * Q[b] @ xsa[b]^T
        gemm(q, xsa, nullptr, h, LL*KH, LL, EE,
             (long)LL*KE, (long)LL*EE, (long)LL*KH*LL, BB, 0, 0, inv_sqrt_e, FL_TRANS);
        softmax512_k<<<BB * LL * KH, 256>>>(h);
        // y[b] = P[b] @ xsa[b]
        gemm(h, xsa, nullptr, y, LL*KH, EE, LL,
             (long)LL*KH*LL, (long)LL*EE, (long)LL*KH*EE, BB, 0, 0, 1.f, 0);
        // yd = relu(y @ wd.T)
        gemm(y,  wd, nullptr, yd,  BL, KE, KE, 0,0,0, 1, 0, 0, 1.f, FL_TRANS | FL_RELU);
        // xid = yd @ wo   (tall-skinny, deep K -> split-K with atomics)
        cudaMemsetAsync(xid, 0, (size_t)BL * EE * sizeof(float));
        gemm(yd, wo, nullptr, xid, BL, EE, KE, 0,0,0, 1, 0, 0, 1.f, 0, /*splitK=*/4);
        // xsa = norm(xsa + 0.05*norm(xsad + xid))
        update_k<<<BL, 256>>>(xsad, xid, xsa);
    }

    // ---- head ----
    gather_lptok_k<<<BB * LMM, 256>>>(xsa, mask, lptok);
    gemm(lptok, Wkc, bkc, xx1, BB*LMM, KNN*EE, EE, 0,0,0, 1, 0, 0, 1.f, FL_TRANS);
    gemm(xx1, xsa, nullptr, tbuf, LMM*KNN, LL, EE,
         (long)LMM*KNN*EE, (long)LL*EE, (long)LMM*KNN*LL, BB, 0, 0, 1.f, FL_TRANS);
    gemm(tbuf, xsa, nullptr, xx2, LMM*KNN, EE, LL,
         (long)LMM*KNN*LL, (long)LL*EE, (long)LMM*KNN*EE, BB, 0, 0, 1.f, 0);
    gemm(xx2, Wem, nullptr, v, BB*LMM*KNN, EE, EE, 0,0,0, 1, 0, 0, 1.f, 0);
    gemm(v, embed, nullptr, logits, BB*LMM*KNN, GG, EE, 0,0,0, 1, 0, 0, 1.f, FL_TRANS);
    lse_k<<<BB * LMM * KNN, 256>>>(logits, lse);
    final_k<<<BB, LMM>>>(logits, lse, unmasked, mask, out);
}